// round 8
// baseline (speedup 1.0000x reference)
#include <cuda_runtime.h>
#include <math_constants.h>

// ---------------------------------------------------------------------------
// ReverseLossLayer: loss = 0.5 * sum_m  min_n || src[n] - tar[m] ||^2
// Exact 1-NN via 2-D (x,y) bucket grid, 48x48 over [-5,5]^2, full z-columns
// per bucket. 5 graph nodes:
//   clear -> build -> query(3x3, store best, flag rn>1) -> fallback -> finish
// Reduction folded into query/fallback via exact fixed-point u64 atomics.
// ---------------------------------------------------------------------------

#define MAX_M 16384
#define G2 48
#define NC2 (G2 * G2)               // 2304 cells
#define CAP 192                     // lambda_max ~ 113; overflow P ~ 1e-11
#define BASEC (-5.0f)
#define INVH 4.8f                   // G2 / 10
#define FIXSCALE 4294967296.0       // 2^32

__device__ int                g_cnt[NC2];
__device__ float4             g_b[NC2 * CAP];     // ~14 MB static scratch
__device__ float              g_min[MAX_M];
__device__ unsigned long long g_acc;
__device__ int                g_flag[MAX_M];
__device__ int                g_flagcnt;

__device__ __forceinline__ int cell_of(float v) {
    int c = (int)floorf((v - BASEC) * INVH);
    return min(max(c, 0), G2 - 1);
}

// Sufficient xy-index radius: any point with d < sqrt(best) lies within
// index distance floor(sqrt(best)*INVH) + 1 (clamping only contracts).
__device__ __forceinline__ int rn_of(float best) {
    if (!(best < CUDART_INF_F)) return 1 << 20;
    return (int)fmaf(sqrtf(best), INVH, 1.001f);
}

__device__ __forceinline__ unsigned long long fix_of(float best) {
    return (unsigned long long)((double)best * FIXSCALE);
}

__global__ void rl_clear_kernel() {
    const int i = blockIdx.x * blockDim.x + threadIdx.x;   // 2304 threads
    if (i < NC2) g_cnt[i] = 0;
    if (i == 0) { g_acc = 0ull; g_flagcnt = 0; }
}

__global__ void rl_build_kernel(const float* __restrict__ src, int N) {
    const int i = blockIdx.x * blockDim.x + threadIdx.x;
    if (i >= N) return;
    const float x = src[3*i], y = src[3*i+1], z = src[3*i+2];
    const int cell = cell_of(x) * G2 + cell_of(y);
    const int slot = atomicAdd(&g_cnt[cell], 1);
    if (slot < CAP) g_b[cell * CAP + slot] = make_float4(x, y, z, 0.0f);
}

// Warp per target: scan 3x3 xy cells, every lane strides each bucket.
__global__ __launch_bounds__(256)
void rl_query_kernel(const float* __restrict__ tar, int M) {
    const int gtid = blockIdx.x * blockDim.x + threadIdx.x;
    const int t = gtid >> 5, lane = gtid & 31;
    if (t >= M) return;

    const float tx = tar[3*t], ty = tar[3*t+1], tz = tar[3*t+2];
    const int cx = cell_of(tx), cy = cell_of(ty);

    float best = CUDART_INF_F;
    #pragma unroll
    for (int dx = -1; dx <= 1; dx++) {
        const int x = cx + dx;
        if (x < 0 || x >= G2) continue;
        #pragma unroll
        for (int dy = -1; dy <= 1; dy++) {
            const int y = cy + dy;
            if (y < 0 || y >= G2) continue;
            const int cell = x * G2 + y;
            const int cnt = min(g_cnt[cell], CAP);
            const float4* __restrict__ p = &g_b[cell * CAP];
            for (int k = lane; k < cnt; k += 32) {
                const float4 s = p[k];
                const float ddx = s.x - tx, ddy = s.y - ty, ddz = s.z - tz;
                best = fminf(best, fmaf(ddz, ddz, fmaf(ddy, ddy, ddx * ddx)));
            }
        }
    }
    #pragma unroll
    for (int o = 16; o > 0; o >>= 1)
        best = fminf(best, __shfl_xor_sync(0xFFFFFFFFu, best, o));

    if (lane == 0) {
        g_min[t] = best;
        if (rn_of(best) <= 1) atomicAdd(&g_acc, fix_of(best));
        else                  g_flag[atomicAdd(&g_flagcnt, 1)] = t;
    }
}

// Warp per flagged target: seed best from the query pass, scan the
// (2R+1)^2 square with LANE-STRIDED points inside each cell (cells serial).
__global__ __launch_bounds__(256)
void rl_fallback_kernel(const float* __restrict__ tar) {
    const int gtid = blockIdx.x * blockDim.x + threadIdx.x;
    const int lane = gtid & 31;
    const int gwarp = gtid >> 5;
    const int nwarps = (gridDim.x * blockDim.x) >> 5;
    const int nf = g_flagcnt;

    for (int fi = gwarp; fi < nf; fi += nwarps) {
        const int t = g_flag[fi];
        const float tx = tar[3*t], ty = tar[3*t+1], tz = tar[3*t+2];
        const int cx = cell_of(tx), cy = cell_of(ty);

        float best = g_min[t];              // seed from query pass
        int Rdone = 1;                      // 3x3 already scanned
        while (true) {
            const int Rn = rn_of(best);
            if (Rn <= Rdone || Rdone >= G2 - 1) break;
            const int R = (Rn < (1 << 20)) ? min(Rn, G2 - 1)
                                           : min(2 * Rdone + 1, G2 - 1);

            float b = CUDART_INF_F;
            const int x0 = max(cx - R, 0), x1 = min(cx + R, G2 - 1);
            const int y0 = max(cy - R, 0), y1 = min(cy + R, G2 - 1);
            for (int x = x0; x <= x1; x++) {
                for (int y = y0; y <= y1; y++) {
                    // skip the already-scanned inner square
                    if (abs(x - cx) <= Rdone && abs(y - cy) <= Rdone) continue;
                    const int cell = x * G2 + y;
                    const int cnt = min(g_cnt[cell], CAP);
                    const float4* __restrict__ p = &g_b[cell * CAP];
                    for (int k = lane; k < cnt; k += 32) {
                        const float4 s = p[k];
                        const float ddx = s.x - tx, ddy = s.y - ty, ddz = s.z - tz;
                        b = fminf(b, fmaf(ddz, ddz, fmaf(ddy, ddy, ddx * ddx)));
                    }
                }
            }
            #pragma unroll
            for (int o = 16; o > 0; o >>= 1)
                b = fminf(b, __shfl_xor_sync(0xFFFFFFFFu, b, o));
            best = fminf(best, b);
            Rdone = R;
        }
        if (lane == 0) atomicAdd(&g_acc, fix_of(best));
    }
}

__global__ void rl_finish_kernel(float* __restrict__ out) {
    out[0] = (float)(0.5 * ((double)g_acc / FIXSCALE));
}

extern "C" void kernel_launch(void* const* d_in, const int* in_sizes, int n_in,
                              void* d_out, int out_size) {
    const float* src = (const float*)d_in[0];   // [N,3]
    const float* tar = (const float*)d_in[1];   // [M,3]
    float* out = (float*)d_out;

    const int N = in_sizes[0] / 3;
    const int M = in_sizes[1] / 3;

    rl_clear_kernel<<<(NC2 + 255) / 256, 256>>>();
    rl_build_kernel<<<(N + 255) / 256, 256>>>(src, N);
    rl_query_kernel<<<(M * 32 + 255) / 256, 256>>>(tar, M);
    rl_fallback_kernel<<<296, 256>>>(tar);
    rl_finish_kernel<<<1, 1>>>(out);
}

// round 9
// speedup vs baseline: 1.9937x; 1.9937x over previous
#include <cuda_runtime.h>
#include <math_constants.h>

// ---------------------------------------------------------------------------
// ReverseLossLayer: loss = 0.5 * sum_m  min_n || src[n] - tar[m] ||^2
// Exact 1-NN via 2-D (x,y) bucket grid, 48x48 over [-5,5]^2, full z-columns
// per bucket. 5 graph nodes:
//   clear -> build -> query(3x3, store best, flag rn>1) -> fallback -> finish
// Fallback: warp per flagged target, CELLS LANE-PARALLEL (empty-tail safe),
// seeded with the query-pass best (no restart-from-INF).
// Reduction folded into query/fallback via exact fixed-point u64 atomics.
// ---------------------------------------------------------------------------

#define MAX_M 16384
#define G2 48
#define NC2 (G2 * G2)               // 2304 cells
#define CAP 192                     // lambda_max ~ 113; overflow P ~ 1e-11
#define BASEC (-5.0f)
#define INVH 4.8f                   // G2 / 10
#define FIXSCALE 4294967296.0       // 2^32

__device__ int                g_cnt[NC2];
__device__ float4             g_b[NC2 * CAP];     // ~14 MB static scratch
__device__ float              g_min[MAX_M];
__device__ unsigned long long g_acc;
__device__ int                g_flag[MAX_M];
__device__ int                g_flagcnt;

__device__ __forceinline__ int cell_of(float v) {
    int c = (int)floorf((v - BASEC) * INVH);
    return min(max(c, 0), G2 - 1);
}

// Sufficient xy-index radius: any point with d < sqrt(best) lies within
// index distance floor(sqrt(best)*INVH) + 1 (clamping only contracts).
__device__ __forceinline__ int rn_of(float best) {
    if (!(best < CUDART_INF_F)) return 1 << 20;
    return (int)fmaf(sqrtf(best), INVH, 1.001f);
}

__device__ __forceinline__ unsigned long long fix_of(float best) {
    return (unsigned long long)((double)best * FIXSCALE);
}

__global__ void rl_clear_kernel() {
    const int i = blockIdx.x * blockDim.x + threadIdx.x;   // 2304 threads
    if (i < NC2) g_cnt[i] = 0;
    if (i == 0) { g_acc = 0ull; g_flagcnt = 0; }
}

__global__ void rl_build_kernel(const float* __restrict__ src, int N) {
    const int i = blockIdx.x * blockDim.x + threadIdx.x;
    if (i >= N) return;
    const float x = src[3*i], y = src[3*i+1], z = src[3*i+2];
    const int cell = cell_of(x) * G2 + cell_of(y);
    const int slot = atomicAdd(&g_cnt[cell], 1);
    if (slot < CAP) g_b[cell * CAP + slot] = make_float4(x, y, z, 0.0f);
}

// Warp per target: scan 3x3 xy cells, every lane strides each bucket.
__global__ __launch_bounds__(256)
void rl_query_kernel(const float* __restrict__ tar, int M) {
    const int gtid = blockIdx.x * blockDim.x + threadIdx.x;
    const int t = gtid >> 5, lane = gtid & 31;
    if (t >= M) return;

    const float tx = tar[3*t], ty = tar[3*t+1], tz = tar[3*t+2];
    const int cx = cell_of(tx), cy = cell_of(ty);

    float best = CUDART_INF_F;
    #pragma unroll
    for (int dx = -1; dx <= 1; dx++) {
        const int x = cx + dx;
        if (x < 0 || x >= G2) continue;
        #pragma unroll
        for (int dy = -1; dy <= 1; dy++) {
            const int y = cy + dy;
            if (y < 0 || y >= G2) continue;
            const int cell = x * G2 + y;
            const int cnt = min(g_cnt[cell], CAP);
            const float4* __restrict__ p = &g_b[cell * CAP];
            for (int k = lane; k < cnt; k += 32) {
                const float4 s = p[k];
                const float ddx = s.x - tx, ddy = s.y - ty, ddz = s.z - tz;
                best = fminf(best, fmaf(ddz, ddz, fmaf(ddy, ddy, ddx * ddx)));
            }
        }
    }
    #pragma unroll
    for (int o = 16; o > 0; o >>= 1)
        best = fminf(best, __shfl_xor_sync(0xFFFFFFFFu, best, o));

    if (lane == 0) {
        g_min[t] = best;
        if (rn_of(best) <= 1) atomicAdd(&g_acc, fix_of(best));
        else                  g_flag[atomicAdd(&g_flagcnt, 1)] = t;
    }
}

// Warp per flagged target: seed best from the query pass; cells of the
// (2R+1)^2 square are striped ACROSS LANES (empty tail cells cost one
// independent cnt load each); each lane serially scans its cells' points
// (contiguous float4 -> MLP). Inner already-scanned square is skipped.
__global__ __launch_bounds__(256)
void rl_fallback_kernel(const float* __restrict__ tar) {
    const int gtid = blockIdx.x * blockDim.x + threadIdx.x;
    const int lane = gtid & 31;
    const int gwarp = gtid >> 5;
    const int nwarps = (gridDim.x * blockDim.x) >> 5;
    const int nf = g_flagcnt;

    for (int fi = gwarp; fi < nf; fi += nwarps) {
        const int t = g_flag[fi];
        const float tx = tar[3*t], ty = tar[3*t+1], tz = tar[3*t+2];
        const int cx = cell_of(tx), cy = cell_of(ty);

        float best = g_min[t];              // seed from query pass
        int Rdone = 1;                      // 3x3 already scanned
        while (true) {
            const int Rn = rn_of(best);
            if (Rn <= Rdone || Rdone >= G2 - 1) break;
            const int R = (Rn < (1 << 20)) ? min(Rn, G2 - 1)
                                           : min(2 * Rdone + 1, G2 - 1);

            float b = CUDART_INF_F;
            const int W2 = 2 * R + 1, ncells = W2 * W2;
            for (int c = lane; c < ncells; c += 32) {
                const int ddx = c / W2 - R;
                const int ddy = c % W2 - R;
                // skip already-scanned inner square
                if (abs(ddx) <= Rdone && abs(ddy) <= Rdone) continue;
                const int x = cx + ddx, y = cy + ddy;
                if (x < 0 || x >= G2 || y < 0 || y >= G2) continue;
                const int cell = x * G2 + y;
                const int cnt = min(g_cnt[cell], CAP);
                const float4* __restrict__ p = &g_b[cell * CAP];
                for (int k = 0; k < cnt; k++) {
                    const float4 s = p[k];
                    const float dx = s.x - tx, dy = s.y - ty, dz = s.z - tz;
                    b = fminf(b, fmaf(dz, dz, fmaf(dy, dy, dx * dx)));
                }
            }
            #pragma unroll
            for (int o = 16; o > 0; o >>= 1)
                b = fminf(b, __shfl_xor_sync(0xFFFFFFFFu, b, o));
            best = fminf(best, b);
            Rdone = R;
        }
        if (lane == 0) atomicAdd(&g_acc, fix_of(best));
    }
}

__global__ void rl_finish_kernel(float* __restrict__ out) {
    out[0] = (float)(0.5 * ((double)g_acc / FIXSCALE));
}

extern "C" void kernel_launch(void* const* d_in, const int* in_sizes, int n_in,
                              void* d_out, int out_size) {
    const float* src = (const float*)d_in[0];   // [N,3]
    const float* tar = (const float*)d_in[1];   // [M,3]
    float* out = (float*)d_out;

    const int N = in_sizes[0] / 3;
    const int M = in_sizes[1] / 3;

    rl_clear_kernel<<<(NC2 + 255) / 256, 256>>>();
    rl_build_kernel<<<(N + 255) / 256, 256>>>(src, N);
    rl_query_kernel<<<(M * 32 + 255) / 256, 256>>>(tar, M);
    rl_fallback_kernel<<<296, 256>>>(tar);
    rl_finish_kernel<<<1, 1>>>(out);
}

// round 10
// speedup vs baseline: 3.9349x; 1.9737x over previous
#include <cuda_runtime.h>
#include <math_constants.h>

// ---------------------------------------------------------------------------
// ReverseLossLayer: loss = 0.5 * sum_m  min_n || src[n] - tar[m] ||^2
// Exact 1-NN via 2-D (x,y) bucket grid, 48x48 over [-5,5]^2.
// 5 graph nodes: clear -> build -> query(3x3) -> fallback -> finish.
// Fallback (loop-free): Rn<=4 -> single ring scan at radius Rn (lane-parallel
// cells); Rn>4 or empty seed -> whole-warp coalesced brute force over all N.
// Reduction folded in via exact fixed-point u64 atomics.
// ---------------------------------------------------------------------------

#define MAX_M 16384
#define G2 48
#define NC2 (G2 * G2)               // 2304 cells
#define CAP 192                     // lambda_max ~ 113; overflow P ~ 1e-11
#define BASEC (-5.0f)
#define INVH 4.8f                   // G2 / 10
#define FIXSCALE 4294967296.0       // 2^32
#define RMAX 4                      // ring-scan cutoff; beyond -> brute force

__device__ int                g_cnt[NC2];
__device__ float4             g_b[NC2 * CAP];     // ~14 MB bucket scratch
__device__ float4             g_all[MAX_M];       // compact unordered copy
__device__ float              g_min[MAX_M];
__device__ unsigned long long g_acc;
__device__ int                g_flag[MAX_M];
__device__ int                g_flagcnt;

__device__ __forceinline__ int cell_of(float v) {
    int c = (int)floorf((v - BASEC) * INVH);
    return min(max(c, 0), G2 - 1);
}

// Sufficient xy-index radius: any point with d < sqrt(best) lies within
// index distance floor(sqrt(best)*INVH) + 1 (clamping only contracts).
__device__ __forceinline__ int rn_of(float best) {
    if (!(best < CUDART_INF_F)) return 1 << 20;
    return (int)fmaf(sqrtf(best), INVH, 1.001f);
}

__device__ __forceinline__ unsigned long long fix_of(float best) {
    return (unsigned long long)((double)best * FIXSCALE);
}

__global__ void rl_clear_kernel() {
    const int i = blockIdx.x * blockDim.x + threadIdx.x;   // 2304 threads
    if (i < NC2) g_cnt[i] = 0;
    if (i == 0) { g_acc = 0ull; g_flagcnt = 0; }
}

__global__ void rl_build_kernel(const float* __restrict__ src, int N) {
    const int i = blockIdx.x * blockDim.x + threadIdx.x;
    if (i >= N) return;
    const float x = src[3*i], y = src[3*i+1], z = src[3*i+2];
    g_all[i] = make_float4(x, y, z, 0.0f);          // compact copy for brute
    const int cell = cell_of(x) * G2 + cell_of(y);
    const int slot = atomicAdd(&g_cnt[cell], 1);
    if (slot < CAP) g_b[cell * CAP + slot] = make_float4(x, y, z, 0.0f);
}

// Warp per target: scan 3x3 xy cells, every lane strides each bucket.
__global__ __launch_bounds__(256)
void rl_query_kernel(const float* __restrict__ tar, int M) {
    const int gtid = blockIdx.x * blockDim.x + threadIdx.x;
    const int t = gtid >> 5, lane = gtid & 31;
    if (t >= M) return;

    const float tx = tar[3*t], ty = tar[3*t+1], tz = tar[3*t+2];
    const int cx = cell_of(tx), cy = cell_of(ty);

    float best = CUDART_INF_F;
    #pragma unroll
    for (int dx = -1; dx <= 1; dx++) {
        const int x = cx + dx;
        if (x < 0 || x >= G2) continue;
        #pragma unroll
        for (int dy = -1; dy <= 1; dy++) {
            const int y = cy + dy;
            if (y < 0 || y >= G2) continue;
            const int cell = x * G2 + y;
            const int cnt = min(g_cnt[cell], CAP);
            const float4* __restrict__ p = &g_b[cell * CAP];
            for (int k = lane; k < cnt; k += 32) {
                const float4 s = p[k];
                const float ddx = s.x - tx, ddy = s.y - ty, ddz = s.z - tz;
                best = fminf(best, fmaf(ddz, ddz, fmaf(ddy, ddy, ddx * ddx)));
            }
        }
    }
    #pragma unroll
    for (int o = 16; o > 0; o >>= 1)
        best = fminf(best, __shfl_xor_sync(0xFFFFFFFFu, best, o));

    if (lane == 0) {
        g_min[t] = best;
        if (rn_of(best) <= 1) atomicAdd(&g_acc, fix_of(best));
        else                  g_flag[atomicAdd(&g_flagcnt, 1)] = t;
    }
}

// Warp per flagged target, loop-free dispatch on Rn from the seeded best.
__global__ __launch_bounds__(256)
void rl_fallback_kernel(const float* __restrict__ tar, int N) {
    const int gtid = blockIdx.x * blockDim.x + threadIdx.x;
    const int lane = gtid & 31;
    const int gwarp = gtid >> 5;
    const int nwarps = (gridDim.x * blockDim.x) >> 5;
    const int nf = g_flagcnt;

    for (int fi = gwarp; fi < nf; fi += nwarps) {
        const int t = g_flag[fi];
        const float tx = tar[3*t], ty = tar[3*t+1], tz = tar[3*t+2];

        float best = g_min[t];               // seed from query pass
        const int Rn = rn_of(best);
        float b = CUDART_INF_F;

        if (Rn <= RMAX) {
            // Single ring scan at radius Rn; inner 3x3 already done.
            const int cx = cell_of(tx), cy = cell_of(ty);
            const int W2 = 2 * Rn + 1, ncells = W2 * W2;
            for (int c = lane; c < ncells; c += 32) {
                const int ddx = c / W2 - Rn;
                const int ddy = c % W2 - Rn;
                if (abs(ddx) <= 1 && abs(ddy) <= 1) continue;
                const int x = cx + ddx, y = cy + ddy;
                if (x < 0 || x >= G2 || y < 0 || y >= G2) continue;
                const int cell = x * G2 + y;
                const int cnt = min(g_cnt[cell], CAP);
                const float4* __restrict__ p = &g_b[cell * CAP];
                for (int k = 0; k < cnt; k++) {
                    const float4 s = p[k];
                    const float dx = s.x - tx, dy = s.y - ty, dz = s.z - tz;
                    b = fminf(b, fmaf(dz, dz, fmaf(dy, dy, dx * dx)));
                }
            }
        } else {
            // Extreme outlier: coalesced whole-warp brute force (exact).
            for (int k = lane; k < N; k += 32) {
                const float4 s = g_all[k];
                const float dx = s.x - tx, dy = s.y - ty, dz = s.z - tz;
                b = fminf(b, fmaf(dz, dz, fmaf(dy, dy, dx * dx)));
            }
        }
        #pragma unroll
        for (int o = 16; o > 0; o >>= 1)
            b = fminf(b, __shfl_xor_sync(0xFFFFFFFFu, b, o));
        best = fminf(best, b);

        if (lane == 0) atomicAdd(&g_acc, fix_of(best));
    }
}

__global__ void rl_finish_kernel(float* __restrict__ out) {
    out[0] = (float)(0.5 * ((double)g_acc / FIXSCALE));
}

extern "C" void kernel_launch(void* const* d_in, const int* in_sizes, int n_in,
                              void* d_out, int out_size) {
    const float* src = (const float*)d_in[0];   // [N,3]
    const float* tar = (const float*)d_in[1];   // [M,3]
    float* out = (float*)d_out;

    const int N = in_sizes[0] / 3;
    const int M = in_sizes[1] / 3;

    rl_clear_kernel<<<(NC2 + 255) / 256, 256>>>();
    rl_build_kernel<<<(N + 255) / 256, 256>>>(src, N);
    rl_query_kernel<<<(M * 32 + 255) / 256, 256>>>(tar, M);
    rl_fallback_kernel<<<296, 256>>>(tar, N);
    rl_finish_kernel<<<1, 1>>>(out);
}

// round 11
// speedup vs baseline: 4.2774x; 1.0870x over previous
#include <cuda_runtime.h>
#include <math_constants.h>

// ---------------------------------------------------------------------------
// ReverseLossLayer: loss = 0.5 * sum_m  min_n || src[n] - tar[m] ||^2
// Exact 1-NN via 2-D (x,y) bucket grid, 48x48 over [-5,5]^2. 6 graph nodes:
//   clear -> build -> query(3x3) -> fallback_ring -> fallback_brute -> finish
// query flags targets whose 3x3 scan is insufficient:
//   Rn in [2,RMAX]  -> ring list  (warp per target, single ring scan at Rn)
//   Rn > RMAX / INF -> extreme list (BLOCK per target, ILP-unrolled brute)
// Reduction folded in via exact fixed-point u64 atomics (order-invariant).
// ---------------------------------------------------------------------------

#define MAX_M 16384
#define G2 48
#define NC2 (G2 * G2)               // 2304 cells
#define CAP 192                     // lambda_max ~ 113; overflow P ~ 1e-11
#define BASEC (-5.0f)
#define INVH 4.8f                   // G2 / 10
#define FIXSCALE 4294967296.0       // 2^32
#define RMAX 4                      // ring cutoff; beyond -> block brute

__device__ int                g_cnt[NC2];
__device__ float4             g_b[NC2 * CAP];     // ~14 MB bucket scratch
__device__ float4             g_all[MAX_M];       // compact unordered copy
__device__ float              g_min[MAX_M];
__device__ unsigned long long g_acc;
__device__ int                g_flag[MAX_M];      // ring targets (Rn 2..RMAX)
__device__ int                g_flagcnt;
__device__ int                g_flag2[MAX_M];     // extreme targets (Rn>RMAX)
__device__ int                g_flag2cnt;

__device__ __forceinline__ int cell_of(float v) {
    int c = (int)floorf((v - BASEC) * INVH);
    return min(max(c, 0), G2 - 1);
}

// Sufficient xy-index radius: any point with d < sqrt(best) lies within
// index distance floor(sqrt(best)*INVH) + 1 (clamping only contracts).
__device__ __forceinline__ int rn_of(float best) {
    if (!(best < CUDART_INF_F)) return 1 << 20;
    return (int)fmaf(sqrtf(best), INVH, 1.001f);
}

__device__ __forceinline__ unsigned long long fix_of(float best) {
    return (unsigned long long)((double)best * FIXSCALE);
}

__global__ void rl_clear_kernel() {
    const int i = blockIdx.x * blockDim.x + threadIdx.x;   // 2304 threads
    if (i < NC2) g_cnt[i] = 0;
    if (i == 0) { g_acc = 0ull; g_flagcnt = 0; g_flag2cnt = 0; }
}

__global__ void rl_build_kernel(const float* __restrict__ src, int N) {
    const int i = blockIdx.x * blockDim.x + threadIdx.x;
    if (i >= N) return;
    const float x = src[3*i], y = src[3*i+1], z = src[3*i+2];
    g_all[i] = make_float4(x, y, z, 0.0f);          // compact copy for brute
    const int cell = cell_of(x) * G2 + cell_of(y);
    const int slot = atomicAdd(&g_cnt[cell], 1);
    if (slot < CAP) g_b[cell * CAP + slot] = make_float4(x, y, z, 0.0f);
}

// Warp per target: scan 3x3 xy cells, every lane strides each bucket.
__global__ __launch_bounds__(256)
void rl_query_kernel(const float* __restrict__ tar, int M) {
    const int gtid = blockIdx.x * blockDim.x + threadIdx.x;
    const int t = gtid >> 5, lane = gtid & 31;
    if (t >= M) return;

    const float tx = tar[3*t], ty = tar[3*t+1], tz = tar[3*t+2];
    const int cx = cell_of(tx), cy = cell_of(ty);

    float best = CUDART_INF_F;
    #pragma unroll
    for (int dx = -1; dx <= 1; dx++) {
        const int x = cx + dx;
        if (x < 0 || x >= G2) continue;
        #pragma unroll
        for (int dy = -1; dy <= 1; dy++) {
            const int y = cy + dy;
            if (y < 0 || y >= G2) continue;
            const int cell = x * G2 + y;
            const int cnt = min(g_cnt[cell], CAP);
            const float4* __restrict__ p = &g_b[cell * CAP];
            for (int k = lane; k < cnt; k += 32) {
                const float4 s = p[k];
                const float ddx = s.x - tx, ddy = s.y - ty, ddz = s.z - tz;
                best = fminf(best, fmaf(ddz, ddz, fmaf(ddy, ddy, ddx * ddx)));
            }
        }
    }
    #pragma unroll
    for (int o = 16; o > 0; o >>= 1)
        best = fminf(best, __shfl_xor_sync(0xFFFFFFFFu, best, o));

    if (lane == 0) {
        g_min[t] = best;
        const int Rn = rn_of(best);
        if (Rn <= 1)         atomicAdd(&g_acc, fix_of(best));
        else if (Rn <= RMAX) g_flag[atomicAdd(&g_flagcnt, 1)] = t;
        else                 g_flag2[atomicAdd(&g_flag2cnt, 1)] = t;
    }
}

// Warp per ring target: single ring scan at radius Rn (2..RMAX), cells
// striped across lanes, inner 3x3 skipped; best seeded from query pass.
__global__ __launch_bounds__(256)
void rl_ring_kernel(const float* __restrict__ tar) {
    const int gtid = blockIdx.x * blockDim.x + threadIdx.x;
    const int lane = gtid & 31;
    const int gwarp = gtid >> 5;
    const int nwarps = (gridDim.x * blockDim.x) >> 5;
    const int nf = g_flagcnt;

    for (int fi = gwarp; fi < nf; fi += nwarps) {
        const int t = g_flag[fi];
        const float tx = tar[3*t], ty = tar[3*t+1], tz = tar[3*t+2];
        const int cx = cell_of(tx), cy = cell_of(ty);

        float best = g_min[t];               // finite, Rn in [2, RMAX]
        const int Rn = rn_of(best);
        float b = CUDART_INF_F;

        const int W2 = 2 * Rn + 1, ncells = W2 * W2;
        for (int c = lane; c < ncells; c += 32) {
            const int ddx = c / W2 - Rn;
            const int ddy = c % W2 - Rn;
            if (abs(ddx) <= 1 && abs(ddy) <= 1) continue;   // inner 3x3 done
            const int x = cx + ddx, y = cy + ddy;
            if (x < 0 || x >= G2 || y < 0 || y >= G2) continue;
            const int cell = x * G2 + y;
            const int cnt = min(g_cnt[cell], CAP);
            const float4* __restrict__ p = &g_b[cell * CAP];
            for (int k = 0; k < cnt; k++) {
                const float4 s = p[k];
                const float dx = s.x - tx, dy = s.y - ty, dz = s.z - tz;
                b = fminf(b, fmaf(dz, dz, fmaf(dy, dy, dx * dx)));
            }
        }
        #pragma unroll
        for (int o = 16; o > 0; o >>= 1)
            b = fminf(b, __shfl_xor_sync(0xFFFFFFFFu, b, o));
        best = fminf(best, b);

        if (lane == 0) atomicAdd(&g_acc, fix_of(best));
    }
}

// BLOCK per extreme target: ILP-unrolled coalesced brute force over all N.
__global__ __launch_bounds__(256)
void rl_brute_kernel(const float* __restrict__ tar, int N) {
    __shared__ float shf[256];
    const int tid = threadIdx.x;
    const int nf2 = g_flag2cnt;

    for (int fi = blockIdx.x; fi < nf2; fi += gridDim.x) {
        const int t = g_flag2[fi];
        const float tx = tar[3*t], ty = tar[3*t+1], tz = tar[3*t+2];

        // 4 independent accumulators -> 4+ loads in flight per thread
        float b0 = CUDART_INF_F, b1 = CUDART_INF_F;
        float b2 = CUDART_INF_F, b3 = CUDART_INF_F;
        int k = tid;
        for (; k + 768 < N; k += 1024) {
            const float4 s0 = g_all[k];
            const float4 s1 = g_all[k + 256];
            const float4 s2 = g_all[k + 512];
            const float4 s3 = g_all[k + 768];
            float dx, dy, dz;
            dx = s0.x - tx; dy = s0.y - ty; dz = s0.z - tz;
            b0 = fminf(b0, fmaf(dz, dz, fmaf(dy, dy, dx * dx)));
            dx = s1.x - tx; dy = s1.y - ty; dz = s1.z - tz;
            b1 = fminf(b1, fmaf(dz, dz, fmaf(dy, dy, dx * dx)));
            dx = s2.x - tx; dy = s2.y - ty; dz = s2.z - tz;
            b2 = fminf(b2, fmaf(dz, dz, fmaf(dy, dy, dx * dx)));
            dx = s3.x - tx; dy = s3.y - ty; dz = s3.z - tz;
            b3 = fminf(b3, fmaf(dz, dz, fmaf(dy, dy, dx * dx)));
        }
        for (; k < N; k += 256) {
            const float4 s = g_all[k];
            const float dx = s.x - tx, dy = s.y - ty, dz = s.z - tz;
            b0 = fminf(b0, fmaf(dz, dz, fmaf(dy, dy, dx * dx)));
        }
        float b = fminf(fminf(b0, b1), fminf(b2, b3));

        shf[tid] = b;
        __syncthreads();
        #pragma unroll
        for (int o = 128; o > 0; o >>= 1) {
            if (tid < o) shf[tid] = fminf(shf[tid], shf[tid + o]);
            __syncthreads();
        }
        if (tid == 0) atomicAdd(&g_acc, fix_of(shf[0]));
        __syncthreads();
    }
}

__global__ void rl_finish_kernel(float* __restrict__ out) {
    out[0] = (float)(0.5 * ((double)g_acc / FIXSCALE));
}

extern "C" void kernel_launch(void* const* d_in, const int* in_sizes, int n_in,
                              void* d_out, int out_size) {
    const float* src = (const float*)d_in[0];   // [N,3]
    const float* tar = (const float*)d_in[1];   // [M,3]
    float* out = (float*)d_out;

    const int N = in_sizes[0] / 3;
    const int M = in_sizes[1] / 3;

    rl_clear_kernel<<<(NC2 + 255) / 256, 256>>>();
    rl_build_kernel<<<(N + 255) / 256, 256>>>(src, N);
    rl_query_kernel<<<(M * 32 + 255) / 256, 256>>>(tar, M);
    rl_ring_kernel<<<296, 256>>>(tar);
    rl_brute_kernel<<<148, 256>>>(tar, N);
    rl_finish_kernel<<<1, 1>>>(out);
}

// round 12
// speedup vs baseline: 5.8465x; 1.3668x over previous
#include <cuda_runtime.h>
#include <math_constants.h>

// ---------------------------------------------------------------------------
// ReverseLossLayer: loss = 0.5 * sum_m  min_n || src[n] - tar[m] ||^2
// Exact 1-NN via 2-D (x,y) bucket grid, 48x48 over [-5,5]^2. 4 graph nodes:
//   build -> query(3x3, flag insufficient) -> fixup(block/target) -> finish
// State contract: g_cnt / g_acc / g_flagcnt are ZERO at entry (CUDA zero-init
// on first call; the finish node re-zeros them for the next replay). Bucket
// slot order is nondeterministic but min over a bucket is order-invariant.
// Reduction uses exact fixed-point u64 atomics (order-invariant).
// ---------------------------------------------------------------------------

#define MAX_M 16384
#define G2 48
#define NC2 (G2 * G2)               // 2304 cells
#define CAP 192                     // lambda_max ~ 113; overflow P ~ 1e-11
#define BASEC (-5.0f)
#define INVH 4.8f                   // G2 / 10
#define FIXSCALE 4294967296.0       // 2^32
#define RMAX 4                      // ring cutoff; beyond -> brute force

__device__ int                g_cnt[NC2];          // zero-init
__device__ float4             g_b[NC2 * CAP];      // ~14 MB bucket scratch
__device__ float4             g_all[MAX_M];        // compact unordered copy
__device__ float              g_min[MAX_M];
__device__ unsigned long long g_acc;               // zero-init
__device__ int                g_flag[MAX_M];
__device__ int                g_flagcnt;           // zero-init

__device__ __forceinline__ int cell_of(float v) {
    int c = (int)floorf((v - BASEC) * INVH);
    return min(max(c, 0), G2 - 1);
}

// Sufficient xy-index radius: any point with d < sqrt(best) lies within
// index distance floor(sqrt(best)*INVH) + 1 (clamping only contracts).
__device__ __forceinline__ int rn_of(float best) {
    if (!(best < CUDART_INF_F)) return 1 << 20;
    return (int)fmaf(sqrtf(best), INVH, 1.001f);
}

__device__ __forceinline__ unsigned long long fix_of(float best) {
    return (unsigned long long)((double)best * FIXSCALE);
}

__global__ void rl_build_kernel(const float* __restrict__ src, int N) {
    const int i = blockIdx.x * blockDim.x + threadIdx.x;
    if (i >= N) return;
    const float x = src[3*i], y = src[3*i+1], z = src[3*i+2];
    g_all[i] = make_float4(x, y, z, 0.0f);          // compact copy for brute
    const int cell = cell_of(x) * G2 + cell_of(y);
    const int slot = atomicAdd(&g_cnt[cell], 1);
    if (slot < CAP) g_b[cell * CAP + slot] = make_float4(x, y, z, 0.0f);
}

// Warp per target: scan 3x3 xy cells, every lane strides each bucket.
__global__ __launch_bounds__(256)
void rl_query_kernel(const float* __restrict__ tar, int M) {
    const int gtid = blockIdx.x * blockDim.x + threadIdx.x;
    const int t = gtid >> 5, lane = gtid & 31;
    if (t >= M) return;

    const float tx = tar[3*t], ty = tar[3*t+1], tz = tar[3*t+2];
    const int cx = cell_of(tx), cy = cell_of(ty);

    float best = CUDART_INF_F;
    #pragma unroll
    for (int dx = -1; dx <= 1; dx++) {
        const int x = cx + dx;
        if (x < 0 || x >= G2) continue;
        #pragma unroll
        for (int dy = -1; dy <= 1; dy++) {
            const int y = cy + dy;
            if (y < 0 || y >= G2) continue;
            const int cell = x * G2 + y;
            const int cnt = min(g_cnt[cell], CAP);
            const float4* __restrict__ p = &g_b[cell * CAP];
            for (int k = lane; k < cnt; k += 32) {
                const float4 s = p[k];
                const float ddx = s.x - tx, ddy = s.y - ty, ddz = s.z - tz;
                best = fminf(best, fmaf(ddz, ddz, fmaf(ddy, ddy, ddx * ddx)));
            }
        }
    }
    #pragma unroll
    for (int o = 16; o > 0; o >>= 1)
        best = fminf(best, __shfl_xor_sync(0xFFFFFFFFu, best, o));

    if (lane == 0) {
        g_min[t] = best;
        if (rn_of(best) <= 1) atomicAdd(&g_acc, fix_of(best));
        else                  g_flag[atomicAdd(&g_flagcnt, 1)] = t;
    }
}

// BLOCK per flagged target. Ring path: 8 threads per cell (coalesced bucket
// reads), 32 cells per round. Brute path (Rn>RMAX or empty seed): 256-thread
// ILP-unrolled scan of the compact point array.
__global__ __launch_bounds__(256)
void rl_fixup_kernel(const float* __restrict__ tar, int N) {
    __shared__ float shf[256];
    const int tid = threadIdx.x;
    const int nf = g_flagcnt;

    for (int fi = blockIdx.x; fi < nf; fi += gridDim.x) {
        const int t = g_flag[fi];
        const float tx = tar[3*t], ty = tar[3*t+1], tz = tar[3*t+2];

        const float seed = g_min[t];
        const int Rn = rn_of(seed);
        float b = CUDART_INF_F;

        if (Rn <= RMAX) {
            // (2Rn+1)^2 cells minus inner 3x3; cell group = tid/8 (32 groups),
            // sub-lane = tid%8 strides the bucket -> coalesced 128B reads.
            const int cx = cell_of(tx), cy = cell_of(ty);
            const int grp = tid >> 3, sub = tid & 7;
            const int W2 = 2 * Rn + 1, ncells = W2 * W2;
            for (int c = grp; c < ncells; c += 32) {
                const int ddx = c / W2 - Rn;
                const int ddy = c % W2 - Rn;
                if (abs(ddx) <= 1 && abs(ddy) <= 1) continue;   // 3x3 done
                const int x = cx + ddx, y = cy + ddy;
                if (x < 0 || x >= G2 || y < 0 || y >= G2) continue;
                const int cell = x * G2 + y;
                const int cnt = min(g_cnt[cell], CAP);
                const float4* __restrict__ p = &g_b[cell * CAP];
                for (int k = sub; k < cnt; k += 8) {
                    const float4 s = p[k];
                    const float dx = s.x - tx, dy = s.y - ty, dz = s.z - tz;
                    b = fminf(b, fmaf(dz, dz, fmaf(dy, dy, dx * dx)));
                }
            }
        } else {
            // Extreme outlier: whole-block brute force, 4-way ILP.
            float b0 = CUDART_INF_F, b1 = CUDART_INF_F;
            float b2 = CUDART_INF_F, b3 = CUDART_INF_F;
            int k = tid;
            for (; k + 768 < N; k += 1024) {
                const float4 s0 = g_all[k];
                const float4 s1 = g_all[k + 256];
                const float4 s2 = g_all[k + 512];
                const float4 s3 = g_all[k + 768];
                float dx, dy, dz;
                dx = s0.x - tx; dy = s0.y - ty; dz = s0.z - tz;
                b0 = fminf(b0, fmaf(dz, dz, fmaf(dy, dy, dx * dx)));
                dx = s1.x - tx; dy = s1.y - ty; dz = s1.z - tz;
                b1 = fminf(b1, fmaf(dz, dz, fmaf(dy, dy, dx * dx)));
                dx = s2.x - tx; dy = s2.y - ty; dz = s2.z - tz;
                b2 = fminf(b2, fmaf(dz, dz, fmaf(dy, dy, dx * dx)));
                dx = s3.x - tx; dy = s3.y - ty; dz = s3.z - tz;
                b3 = fminf(b3, fmaf(dz, dz, fmaf(dy, dy, dx * dx)));
            }
            for (; k < N; k += 256) {
                const float4 s = g_all[k];
                const float dx = s.x - tx, dy = s.y - ty, dz = s.z - tz;
                b0 = fminf(b0, fmaf(dz, dz, fmaf(dy, dy, dx * dx)));
            }
            b = fminf(fminf(b0, b1), fminf(b2, b3));
        }

        shf[tid] = b;
        __syncthreads();
        #pragma unroll
        for (int o = 128; o > 0; o >>= 1) {
            if (tid < o) shf[tid] = fminf(shf[tid], shf[tid + o]);
            __syncthreads();
        }
        if (tid == 0) atomicAdd(&g_acc, fix_of(fminf(shf[0], seed)));
        __syncthreads();
    }
}

// Writes the result AND resets all mutated persistent state so that the next
// graph replay starts from the same (zeroed) state as the first call.
__global__ void rl_finish_kernel(float* __restrict__ out) {
    const int tid = threadIdx.x;
    if (tid == 0) {
        out[0] = (float)(0.5 * ((double)g_acc / FIXSCALE));
        g_acc = 0ull;
        g_flagcnt = 0;
    }
    for (int i = tid; i < NC2; i += blockDim.x)
        g_cnt[i] = 0;
}

extern "C" void kernel_launch(void* const* d_in, const int* in_sizes, int n_in,
                              void* d_out, int out_size) {
    const float* src = (const float*)d_in[0];   // [N,3]
    const float* tar = (const float*)d_in[1];   // [M,3]
    float* out = (float*)d_out;

    const int N = in_sizes[0] / 3;
    const int M = in_sizes[1] / 3;

    rl_build_kernel<<<(N + 255) / 256, 256>>>(src, N);
    rl_query_kernel<<<(M * 32 + 255) / 256, 256>>>(tar, M);
    rl_fixup_kernel<<<296, 256>>>(tar, N);
    rl_finish_kernel<<<1, 256>>>(out);
}